// round 9
// baseline (speedup 1.0000x reference)
#include <cuda_runtime.h>
#include <math.h>
#include <stdint.h>

// Problem constants
#define BB    256
#define HH    6
#define NN    2048
#define MM    64
#define DIN   128
#define WFLAT 12288          // H*N
#define DCAT  12416
#define DOUT  384
#define Y_N   1152           // 3*DOUT
#define MEM_ELEMS 131072     // N*M per batch
#define OUT_MEM_TOTAL 33554432  // B*N*M

// GEMM config (R7, measured 56.4us): CTA 128x64, warp 64x32, BKT=32, cp.async
#define SPLITK 16
#define BKT 32
#define BMT 128
#define BNT 64
#define ASTR 36
#define BSTR 72
#define A_TILE_F (BMT * ASTR)
#define B_TILE_F (BKT * BSTR)
#define GEMM_SMEM_BYTES ((2 * (A_TILE_F + B_TILE_F)) * 4)   // 55296

// Scratch (static device memory; no allocation)
__device__ float g_Ypart[SPLITK * (size_t)BB * Y_N];  // 18.9 MB
__device__ float g_Ks[BB * DOUT];
__device__ float g_Es[BB * DOUT];
__device__ float g_As[BB * DOUT];
__device__ float g_S[(size_t)BB * NN * 8];            // 16.8 MB exp-scores [b][n][8]
__device__ float g_psum[BB * 2 * HH];                 // per-(b,half,h) partial sums

__device__ __forceinline__ unsigned s2u(const void* p) {
    return (unsigned)__cvta_generic_to_shared(p);
}

__device__ __forceinline__ void cpa16(uint32_t dst, const void* src) {
    asm volatile("cp.async.cg.shared.global [%0], [%1], 16;" :: "r"(dst), "l"(src));
}
#define CP_COMMIT() asm volatile("cp.async.commit_group;" ::: "memory")
#define CP_WAIT1()  asm volatile("cp.async.wait_group 1;" ::: "memory")

#define MMA_TF32(c, a, b0, b1)                                                     \
    asm volatile(                                                                  \
        "mma.sync.aligned.m16n8k8.row.col.f32.tf32.tf32.f32 "                      \
        "{%0,%1,%2,%3},{%4,%5,%6,%7},{%8,%9},{%0,%1,%2,%3};"                       \
        : "+f"(c[0]), "+f"(c[1]), "+f"(c[2]), "+f"(c[3])                           \
        : "r"(a[0]), "r"(a[1]), "r"(a[2]), "r"(a[3]), "r"(b0), "r"(b1))

#define LDSM_X4(r, addr)                                                           \
    asm volatile("ldmatrix.sync.aligned.m8n8.x4.shared.b16 {%0,%1,%2,%3}, [%4];"   \
                 : "=r"(r[0]), "=r"(r[1]), "=r"(r[2]), "=r"(r[3]) : "r"(addr))

// ---------------------------------------------------------------------------
// K1: split-K tf32 GEMM (R7 verbatim)
// ---------------------------------------------------------------------------
__global__ __launch_bounds__(128) void gemm_kernel(
    const float* __restrict__ xw, const float* __restrict__ xin,
    const float* __restrict__ Wk, const float* __restrict__ We,
    const float* __restrict__ Wa)
{
    extern __shared__ float smf[];
    float* As[2] = {smf, smf + A_TILE_F};
    float* Bs[2] = {smf + 2 * A_TILE_F, smf + 2 * A_TILE_F + B_TILE_F};
    const uint32_t sA32[2] = {s2u(As[0]), s2u(As[1])};
    const uint32_t sB32[2] = {s2u(Bs[0]), s2u(Bs[1])};

    const int tid = threadIdx.x;
    const int mt = blockIdx.x, nt = blockIdx.y, z = blockIdx.z;
    const int m0 = mt * BMT;
    const int mat = nt / 6;
    const int n0col = (nt % 6) * BNT;
    const float* __restrict__ Wp = (mat == 0) ? Wk : ((mat == 1) ? We : Wa);

    const int baseT = z * 24 + min(z, 4);
    const int cnt   = 24 + (z < 4 ? 1 : 0);
    const int k0    = baseT * BKT;

    const int wid = tid >> 5, lane = tid & 31;
    const int g = lane >> 2, t = lane & 3;
    const int wm = (wid & 1) * 64, wn = (wid >> 1) * 32;

    const int aRowOff = (lane & 15) * ASTR + (lane >> 4) * 4;

    const int arow = tid >> 3;
    const int ac4  = (tid & 7) * 4;
    const int brow = tid >> 4;
    const int bc4  = (tid & 15) * 4;

    float acc[4][4][4];
#pragma unroll
    for (int i = 0; i < 4; i++)
#pragma unroll
        for (int j = 0; j < 4; j++)
#pragma unroll
            for (int q = 0; q < 4; q++) acc[i][j][q] = 0.0f;

#define LOADT(it)                                                                  \
    do {                                                                           \
        const int buf = (it) & 1;                                                  \
        int kb = k0 + (it) * BKT;                                                  \
        int kg = kb + ac4;                                                         \
        _Pragma("unroll")                                                          \
        for (int i = 0; i < 8; i++) {                                              \
            int row = arow + i * 16;                                               \
            uint32_t dst = sA32[buf] + 4u * (row * ASTR + ac4);                    \
            const float* src = (kg < WFLAT)                                        \
                ? (xw + (size_t)(m0 + row) * WFLAT + kg)                           \
                : (xin + (size_t)(m0 + row) * DIN + (kg - WFLAT));                 \
            cpa16(dst, src);                                                       \
        }                                                                          \
        _Pragma("unroll")                                                          \
        for (int i = 0; i < 4; i++) {                                              \
            int kr = brow + i * 8;                                                 \
            uint32_t dst = sB32[buf] + 4u * (kr * BSTR + bc4);                     \
            cpa16(dst, Wp + (size_t)(kb + kr) * DOUT + n0col + bc4);               \
        }                                                                          \
    } while (0)

    LOADT(0);
    CP_COMMIT();
    if (cnt > 1) LOADT(1);
    CP_COMMIT();

    for (int it = 0; it < cnt; ++it) {
        CP_WAIT1();
        __syncthreads();

        const int bf = it & 1;
        const uint32_t sA = sA32[bf];
        const float* __restrict__ Bsf = Bs[bf];
#pragma unroll
        for (int ko = 0; ko < BKT; ko += 8) {
            unsigned af[4][4];
#pragma unroll
            for (int mf = 0; mf < 4; mf++) {
                unsigned addr = sA + 4u * ((wm + mf * 16) * ASTR + aRowOff + ko);
                LDSM_X4(af[mf], addr);
            }
            unsigned bfr[4][2];
#pragma unroll
            for (int nf = 0; nf < 4; nf++) {
                int c0 = wn + nf * 8 + g;
                bfr[nf][0] = __float_as_uint(Bsf[(ko + t) * BSTR + c0]);
                bfr[nf][1] = __float_as_uint(Bsf[(ko + t + 4) * BSTR + c0]);
            }
#pragma unroll
            for (int mf = 0; mf < 4; mf++)
#pragma unroll
                for (int nf = 0; nf < 4; nf++)
                    MMA_TF32(acc[mf][nf], af[mf], bfr[nf][0], bfr[nf][1]);
        }

        __syncthreads();
        if (it + 2 < cnt) LOADT(it + 2);
        CP_COMMIT();
    }

    float* yp = g_Ypart + (size_t)z * (BB * Y_N);
#pragma unroll
    for (int mf = 0; mf < 4; mf++) {
#pragma unroll
        for (int nf = 0; nf < 4; nf++) {
            int row = m0 + wm + mf * 16 + g;
            int col = nt * BNT + wn + nf * 8 + 2 * t;
            float2 v0 = make_float2(acc[mf][nf][0], acc[mf][nf][1]);
            float2 v1 = make_float2(acc[mf][nf][2], acc[mf][nf][3]);
            *(float2*)(yp + (size_t)row * Y_N + col) = v0;
            *(float2*)(yp + (size_t)(row + 8) * Y_N + col) = v1;
        }
    }
#undef LOADT
}

// ---------------------------------------------------------------------------
// K1b: reduce split-K partials, add bias, apply sigmoid for e/a
// ---------------------------------------------------------------------------
__global__ void reduce_act_kernel(const float* __restrict__ bk,
                                  const float* __restrict__ be,
                                  const float* __restrict__ ba)
{
    int idx = blockIdx.x * blockDim.x + threadIdx.x;
    float s = 0.0f;
#pragma unroll
    for (int z = 0; z < SPLITK; z++)
        s += g_Ypart[(size_t)z * (BB * Y_N) + idx];
    int row = idx / Y_N;
    int col = idx - row * Y_N;
    int mat = col / DOUT;
    int c = col - mat * DOUT;
    if (mat == 0) {
        g_Ks[row * DOUT + c] = s + bk[c];
    } else if (mat == 1) {
        float v = s + be[c];
        g_Es[row * DOUT + c] = 1.0f / (1.0f + __expf(-v));
    } else {
        float v = s + ba[c];
        g_As[row * DOUT + c] = 1.0f / (1.0f + __expf(-v));
    }
}

// ---------------------------------------------------------------------------
// K2a: exp(cosine scores) -> g_S[b][n][8], plus per-(b,half,head) sums.
// Scores bounded in [-1,1] so exp without max-subtraction is safe.
// grid (2, 256), 256 threads (8 warps), ~36 KB smem
// ---------------------------------------------------------------------------
#define TSTRIDE 68
__global__ __launch_bounds__(256) void scores_kernel(
    const float* __restrict__ memory)
{
    __shared__ float kn[DOUT];
    __shared__ float tile[8 * 16 * TSTRIDE];
    __shared__ float redp[8][8];   // [warp][head]

    const int b = blockIdx.y;
    const int half = blockIdx.x;
    const int tid = threadIdx.x, wid = tid >> 5, lane = tid & 31;
    const int g = lane >> 2, t = lane & 3;

    // normalized k
    if (wid < HH) {
        float k0 = g_Ks[b * DOUT + wid * 64 + 2 * lane];
        float k1 = g_Ks[b * DOUT + wid * 64 + 2 * lane + 1];
        float ss = k0 * k0 + k1 * k1;
#pragma unroll
        for (int o = 16; o > 0; o >>= 1) ss += __shfl_xor_sync(0xffffffffu, ss, o);
        float rn = rsqrtf(ss);
        kn[wid * 64 + 2 * lane]     = k0 * rn;
        kn[wid * 64 + 2 * lane + 1] = k1 * rn;
    }
    __syncthreads();

    // B fragments (cols 6,7 zero)
    unsigned kb0[8], kb1[8];
#pragma unroll
    for (int c = 0; c < 8; c++) {
        float v0 = (g < HH) ? kn[g * 64 + c * 8 + t] : 0.0f;
        float v1 = (g < HH) ? kn[g * 64 + c * 8 + t + 4] : 0.0f;
        kb0[c] = __float_as_uint(v0);
        kb1[c] = __float_as_uint(v1);
    }

    const float* __restrict__ memb = memory + (size_t)b * MEM_ELEMS;
    float* tileF = tile + wid * 16 * TSTRIDE;
    float4* tf4 = (float4*)tileF;

    float sum0 = 0.0f, sum1 = 0.0f;   // heads 2t, 2t+1

    for (int j = 0; j < 8; j++) {
        const int n0 = half * 1024 + wid * 16 + j * 128;
#pragma unroll
        for (int i = 0; i < 8; i++) {
            int idx = lane + i * 32;
            int row = idx >> 4, q = idx & 15;
            tf4[row * 17 + q] =
                *(const float4*)(memb + (size_t)(n0 + row) * MM + q * 4);
        }
        __syncwarp();

        float acc[4] = {0.f, 0.f, 0.f, 0.f};
        float ss0 = 0.f, ss1 = 0.f;
#pragma unroll
        for (int c = 0; c < 8; c++) {
            float a0 = tileF[g * TSTRIDE + c * 8 + t];
            float a1 = tileF[(g + 8) * TSTRIDE + c * 8 + t];
            float a2 = tileF[g * TSTRIDE + c * 8 + t + 4];
            float a3 = tileF[(g + 8) * TSTRIDE + c * 8 + t + 4];
            ss0 += a0 * a0 + a2 * a2;
            ss1 += a1 * a1 + a3 * a3;
            unsigned af[4] = {__float_as_uint(a0), __float_as_uint(a1),
                              __float_as_uint(a2), __float_as_uint(a3)};
            MMA_TF32(acc, af, kb0[c], kb1[c]);
        }
        ss0 += __shfl_xor_sync(0xffffffffu, ss0, 1);
        ss0 += __shfl_xor_sync(0xffffffffu, ss0, 2);
        ss1 += __shfl_xor_sync(0xffffffffu, ss1, 1);
        ss1 += __shfl_xor_sync(0xffffffffu, ss1, 2);
        float rn0 = rsqrtf(ss0), rn1 = rsqrtf(ss1);

        float e0 = __expf(acc[0] * rn0);   // head 2t,   row n0+g
        float e1 = __expf(acc[1] * rn0);   // head 2t+1, row n0+g
        float e2 = __expf(acc[2] * rn1);   // head 2t,   row n0+g+8
        float e3 = __expf(acc[3] * rn1);   // head 2t+1, row n0+g+8
        sum0 += e0 + e2;
        sum1 += e1 + e3;

        float* s0 = g_S + ((size_t)b * NN + n0 + g) * 8 + 2 * t;
        float* s1 = g_S + ((size_t)b * NN + n0 + g + 8) * 8 + 2 * t;
        *(float2*)s0 = make_float2(e0, e1);
        *(float2*)s1 = make_float2(e2, e3);
        __syncwarp();
    }

    // reduce sums across the 8 g-lanes sharing t (lane = g*4 + t)
#pragma unroll
    for (int o = 4; o < 32; o <<= 1) {
        sum0 += __shfl_xor_sync(0xffffffffu, sum0, o);
        sum1 += __shfl_xor_sync(0xffffffffu, sum1, o);
    }
    if (g == 0 && t < 3) {
        redp[wid][2 * t]     = sum0;
        redp[wid][2 * t + 1] = sum1;
    }
    __syncthreads();
    if (tid < HH) {
        float s = 0.0f;
#pragma unroll
        for (int wq = 0; wq < 8; wq++) s += redp[wq][tid];
        g_psum[(b * 2 + half) * HH + tid] = s;
    }
}

// ---------------------------------------------------------------------------
// K2c: memory update via mma + out_w write. grid (4, 256), 128 threads,
// no block barriers. Normalization folded in via inv[h] from g_psum.
// ---------------------------------------------------------------------------
__global__ __launch_bounds__(128) void update_kernel(
    const float* __restrict__ memory, float* __restrict__ out_mem,
    float* __restrict__ out_w)
{
    const int b = blockIdx.y;
    const int ntile = blockIdx.x;
    const int tid = threadIdx.x, wid = tid >> 5, lane = tid & 31;
    const int g = lane >> 2, t = lane & 3;

    // softmax denominators
    float inv[HH];
#pragma unroll
    for (int h = 0; h < HH; h++)
        inv[h] = 1.0f / (g_psum[(b * 2 + 0) * HH + h] +
                         g_psum[(b * 2 + 1) * HH + h]);
    const float i0t = inv[t > 3 ? 0 : t];             // head t (t<4 always valid: t in 0..3)
    const float i1t = (t < 2) ? inv[t + 4] : 0.0f;    // head t+4, else pad->0

    // B fragments from e/a (rows=head, cols=m); rows 6,7 zero
    const float* __restrict__ eb = g_Es + b * DOUT;
    const float* __restrict__ ab = g_As + b * DOUT;
    unsigned eb0[8], eb1[8], ab0[8], ab1[8];
#pragma unroll
    for (int mb = 0; mb < 8; mb++) {
        eb0[mb] = __float_as_uint(eb[t * 64 + mb * 8 + g]);
        ab0[mb] = __float_as_uint(ab[t * 64 + mb * 8 + g]);
        eb1[mb] = __float_as_uint((t < 2) ? eb[(t + 4) * 64 + mb * 8 + g] : 0.0f);
        ab1[mb] = __float_as_uint((t < 2) ? ab[(t + 4) * 64 + mb * 8 + g] : 0.0f);
    }

    const float* __restrict__ memb = memory + (size_t)b * MEM_ELEMS;
    float* __restrict__ outm = out_mem + (size_t)b * MEM_ELEMS;
    const float* __restrict__ wsb = g_S + (size_t)b * NN * 8;

    for (int j = 0; j < 8; j++) {
        const int n0 = ntile * 512 + wid * 16 + j * 64;
        const float* ws = wsb + (size_t)n0 * 8;

        // out_w for these 16 rows (lanes 0..15, one row each)
        if (lane < 16) {
            int row = n0 + lane;
            const float* wr = wsb + (size_t)row * 8;
#pragma unroll
            for (int h = 0; h < HH; h++)
                out_w[((size_t)b * HH + h) * NN + row] = wr[h] * inv[h];
        }

        // A fragment: normalized weights (pad cols scaled to 0)
        unsigned af[4];
        af[0] = __float_as_uint(ws[g * 8 + t] * i0t);
        af[1] = __float_as_uint(ws[(g + 8) * 8 + t] * i0t);
        af[2] = __float_as_uint(ws[g * 8 + t + 4] * i1t);
        af[3] = __float_as_uint(ws[(g + 8) * 8 + t + 4] * i1t);

        const float* mrow0 = memb + (size_t)(n0 + g) * MM;
        const float* mrow1 = memb + (size_t)(n0 + g + 8) * MM;
        float* orow0 = outm + (size_t)(n0 + g) * MM;
        float* orow1 = outm + (size_t)(n0 + g + 8) * MM;

#pragma unroll
        for (int mbh = 0; mbh < 2; mbh++) {
            float er[4][4], ad[4][4];
#pragma unroll
            for (int m2 = 0; m2 < 4; m2++) {
#pragma unroll
                for (int q = 0; q < 4; q++) { er[m2][q] = 0.f; ad[m2][q] = 0.f; }
                int mb = mbh * 4 + m2;
                MMA_TF32(er[m2], af, eb0[mb], eb1[mb]);
                MMA_TF32(ad[m2], af, ab0[mb], ab1[mb]);
            }
#pragma unroll
            for (int m2 = 0; m2 < 4; m2++) {
                int mb = mbh * 4 + m2;
                float2 m0v = *(const float2*)(mrow0 + mb * 8 + 2 * t);
                float2 m1v = *(const float2*)(mrow1 + mb * 8 + 2 * t);
                float2 o0, o1;
                o0.x = m0v.x + (ad[m2][0] - m0v.x * m0v.x * er[m2][0]);
                o0.y = m0v.y + (ad[m2][1] - m0v.y * m0v.y * er[m2][1]);
                o1.x = m1v.x + (ad[m2][2] - m1v.x * m1v.x * er[m2][2]);
                o1.y = m1v.y + (ad[m2][3] - m1v.y * m1v.y * er[m2][3]);
                *(float2*)(orow0 + mb * 8 + 2 * t) = o0;
                *(float2*)(orow1 + mb * 8 + 2 * t) = o1;
            }
        }
    }
}

// ---------------------------------------------------------------------------
extern "C" void kernel_launch(void* const* d_in, const int* in_sizes, int n_in,
                              void* d_out, int out_size)
{
    const float* inputs = (const float*)d_in[0];
    const float* memory = (const float*)d_in[1];
    const float* w      = (const float*)d_in[2];
    const float* Wk     = (const float*)d_in[3];
    const float* bk     = (const float*)d_in[4];
    const float* We     = (const float*)d_in[5];
    const float* be     = (const float*)d_in[6];
    const float* Wa     = (const float*)d_in[7];
    const float* ba     = (const float*)d_in[8];

    float* out     = (float*)d_out;
    float* out_mem = out;                       // new_memory [B,N,M]
    float* out_w   = out + OUT_MEM_TOTAL;       // w_new      [B,H,N]

    cudaFuncSetAttribute(gemm_kernel,
                         cudaFuncAttributeMaxDynamicSharedMemorySize,
                         GEMM_SMEM_BYTES);
    dim3 g1(2, 18, SPLITK);
    gemm_kernel<<<g1, 128, GEMM_SMEM_BYTES>>>(w, inputs, Wk, We, Wa);

    reduce_act_kernel<<<(BB * Y_N) / 256, 256>>>(bk, be, ba);

    scores_kernel<<<dim3(2, BB), 256>>>(memory);

    update_kernel<<<dim3(4, BB), 128>>>(memory, out_mem, out_w);
}

// round 10
// speedup vs baseline: 1.0792x; 1.0792x over previous
#include <cuda_runtime.h>
#include <math.h>
#include <stdint.h>

// Problem constants
#define BB    256
#define HH    6
#define NN    2048
#define MM    64
#define DIN   128
#define WFLAT 12288          // H*N
#define DCAT  12416
#define DOUT  384
#define Y_N   1152           // 3*DOUT
#define MEM_ELEMS 131072     // N*M per batch
#define OUT_MEM_TOTAL 33554432  // B*N*M

// GEMM config (R7, measured 56.4us): CTA 128x64, warp 64x32, BKT=32, cp.async
#define SPLITK 16
#define BKT 32
#define BMT 128
#define BNT 64
#define ASTR 36
#define BSTR 72
#define A_TILE_F (BMT * ASTR)
#define B_TILE_F (BKT * BSTR)
#define GEMM_SMEM_BYTES ((2 * (A_TILE_F + B_TILE_F)) * 4)   // 55296

// Scratch (static device memory; no allocation)
__device__ float g_Ypart[SPLITK * (size_t)BB * Y_N];  // 18.9 MB
__device__ float g_Ks[BB * DOUT];
__device__ float g_Es[BB * DOUT];
__device__ float g_As[BB * DOUT];
__device__ float g_S[(size_t)BB * NN * 8];            // 16.8 MB exp-scores [b][n][8]
__device__ float g_psum[BB * 2 * HH];                 // per-(b,half,h) partial sums

__device__ __forceinline__ unsigned s2u(const void* p) {
    return (unsigned)__cvta_generic_to_shared(p);
}

__device__ __forceinline__ void cpa16(uint32_t dst, const void* src) {
    asm volatile("cp.async.cg.shared.global [%0], [%1], 16;" :: "r"(dst), "l"(src));
}
#define CP_COMMIT() asm volatile("cp.async.commit_group;" ::: "memory")
#define CP_WAIT1()  asm volatile("cp.async.wait_group 1;" ::: "memory")

#define MMA_TF32(c, a, b0, b1)                                                     \
    asm volatile(                                                                  \
        "mma.sync.aligned.m16n8k8.row.col.f32.tf32.tf32.f32 "                      \
        "{%0,%1,%2,%3},{%4,%5,%6,%7},{%8,%9},{%0,%1,%2,%3};"                       \
        : "+f"(c[0]), "+f"(c[1]), "+f"(c[2]), "+f"(c[3])                           \
        : "r"(a[0]), "r"(a[1]), "r"(a[2]), "r"(a[3]), "r"(b0), "r"(b1))

#define LDSM_X4(r, addr)                                                           \
    asm volatile("ldmatrix.sync.aligned.m8n8.x4.shared.b16 {%0,%1,%2,%3}, [%4];"   \
                 : "=r"(r[0]), "=r"(r[1]), "=r"(r[2]), "=r"(r[3]) : "r"(addr))

// ---------------------------------------------------------------------------
// K1: split-K tf32 GEMM (R7 verbatim)
// ---------------------------------------------------------------------------
__global__ __launch_bounds__(128) void gemm_kernel(
    const float* __restrict__ xw, const float* __restrict__ xin,
    const float* __restrict__ Wk, const float* __restrict__ We,
    const float* __restrict__ Wa)
{
    extern __shared__ float smf[];
    float* As[2] = {smf, smf + A_TILE_F};
    float* Bs[2] = {smf + 2 * A_TILE_F, smf + 2 * A_TILE_F + B_TILE_F};
    const uint32_t sA32[2] = {s2u(As[0]), s2u(As[1])};
    const uint32_t sB32[2] = {s2u(Bs[0]), s2u(Bs[1])};

    const int tid = threadIdx.x;
    const int mt = blockIdx.x, nt = blockIdx.y, z = blockIdx.z;
    const int m0 = mt * BMT;
    const int mat = nt / 6;
    const int n0col = (nt % 6) * BNT;
    const float* __restrict__ Wp = (mat == 0) ? Wk : ((mat == 1) ? We : Wa);

    const int baseT = z * 24 + min(z, 4);
    const int cnt   = 24 + (z < 4 ? 1 : 0);
    const int k0    = baseT * BKT;

    const int wid = tid >> 5, lane = tid & 31;
    const int g = lane >> 2, t = lane & 3;
    const int wm = (wid & 1) * 64, wn = (wid >> 1) * 32;

    const int aRowOff = (lane & 15) * ASTR + (lane >> 4) * 4;

    const int arow = tid >> 3;
    const int ac4  = (tid & 7) * 4;
    const int brow = tid >> 4;
    const int bc4  = (tid & 15) * 4;

    float acc[4][4][4];
#pragma unroll
    for (int i = 0; i < 4; i++)
#pragma unroll
        for (int j = 0; j < 4; j++)
#pragma unroll
            for (int q = 0; q < 4; q++) acc[i][j][q] = 0.0f;

#define LOADT(it)                                                                  \
    do {                                                                           \
        const int buf = (it) & 1;                                                  \
        int kb = k0 + (it) * BKT;                                                   \
        int kg = kb + ac4;                                                         \
        _Pragma("unroll")                                                          \
        for (int i = 0; i < 8; i++) {                                              \
            int row = arow + i * 16;                                               \
            uint32_t dst = sA32[buf] + 4u * (row * ASTR + ac4);                    \
            const float* src = (kg < WFLAT)                                        \
                ? (xw + (size_t)(m0 + row) * WFLAT + kg)                           \
                : (xin + (size_t)(m0 + row) * DIN + (kg - WFLAT));                 \
            cpa16(dst, src);                                                       \
        }                                                                          \
        _Pragma("unroll")                                                          \
        for (int i = 0; i < 4; i++) {                                              \
            int kr = brow + i * 8;                                                 \
            uint32_t dst = sB32[buf] + 4u * (kr * BSTR + bc4);                     \
            cpa16(dst, Wp + (size_t)(kb + kr) * DOUT + n0col + bc4);               \
        }                                                                          \
    } while (0)

    LOADT(0);
    CP_COMMIT();
    if (cnt > 1) LOADT(1);
    CP_COMMIT();

    for (int it = 0; it < cnt; ++it) {
        CP_WAIT1();
        __syncthreads();

        const int bf = it & 1;
        const uint32_t sA = sA32[bf];
        const float* __restrict__ Bsf = Bs[bf];
#pragma unroll
        for (int ko = 0; ko < BKT; ko += 8) {
            unsigned af[4][4];
#pragma unroll
            for (int mf = 0; mf < 4; mf++) {
                unsigned addr = sA + 4u * ((wm + mf * 16) * ASTR + aRowOff + ko);
                LDSM_X4(af[mf], addr);
            }
            unsigned bfr[4][2];
#pragma unroll
            for (int nf = 0; nf < 4; nf++) {
                int c0 = wn + nf * 8 + g;
                bfr[nf][0] = __float_as_uint(Bsf[(ko + t) * BSTR + c0]);
                bfr[nf][1] = __float_as_uint(Bsf[(ko + t + 4) * BSTR + c0]);
            }
#pragma unroll
            for (int mf = 0; mf < 4; mf++)
#pragma unroll
                for (int nf = 0; nf < 4; nf++)
                    MMA_TF32(acc[mf][nf], af[mf], bfr[nf][0], bfr[nf][1]);
        }

        __syncthreads();
        if (it + 2 < cnt) LOADT(it + 2);
        CP_COMMIT();
    }

    float* yp = g_Ypart + (size_t)z * (BB * Y_N);
#pragma unroll
    for (int mf = 0; mf < 4; mf++) {
#pragma unroll
        for (int nf = 0; nf < 4; nf++) {
            int row = m0 + wm + mf * 16 + g;
            int col = nt * BNT + wn + nf * 8 + 2 * t;
            float2 v0 = make_float2(acc[mf][nf][0], acc[mf][nf][1]);
            float2 v1 = make_float2(acc[mf][nf][2], acc[mf][nf][3]);
            *(float2*)(yp + (size_t)row * Y_N + col) = v0;
            *(float2*)(yp + (size_t)(row + 8) * Y_N + col) = v1;
        }
    }
#undef LOADT
}

// ---------------------------------------------------------------------------
// K1b: reduce split-K partials, add bias, apply sigmoid for e/a
// ---------------------------------------------------------------------------
__global__ void reduce_act_kernel(const float* __restrict__ bk,
                                  const float* __restrict__ be,
                                  const float* __restrict__ ba)
{
    int idx = blockIdx.x * blockDim.x + threadIdx.x;
    float s = 0.0f;
#pragma unroll
    for (int z = 0; z < SPLITK; z++)
        s += g_Ypart[(size_t)z * (BB * Y_N) + idx];
    int row = idx / Y_N;
    int col = idx - row * Y_N;
    int mat = col / DOUT;
    int c = col - mat * DOUT;
    if (mat == 0) {
        g_Ks[row * DOUT + c] = s + bk[c];
    } else if (mat == 1) {
        float v = s + be[c];
        g_Es[row * DOUT + c] = 1.0f / (1.0f + __expf(-v));
    } else {
        float v = s + ba[c];
        g_As[row * DOUT + c] = 1.0f / (1.0f + __expf(-v));
    }
}

// ---------------------------------------------------------------------------
// K2a: exp(cosine scores) -> g_S[b][n][8], plus per-(b,half,head) sums.
// Scores bounded in [-1,1] so exp without max-subtraction is safe.
// grid (2, 256), 256 threads (8 warps), ~36 KB smem
// ---------------------------------------------------------------------------
#define TSTRIDE 68
__global__ __launch_bounds__(256) void scores_kernel(
    const float* __restrict__ memory)
{
    __shared__ float kn[DOUT];
    __shared__ float tile[8 * 16 * TSTRIDE];
    __shared__ float redp[8][8];   // [warp][head]

    const int b = blockIdx.y;
    const int half = blockIdx.x;
    const int tid = threadIdx.x, wid = tid >> 5, lane = tid & 31;
    const int g = lane >> 2, t = lane & 3;

    // normalized k
    if (wid < HH) {
        float k0 = g_Ks[b * DOUT + wid * 64 + 2 * lane];
        float k1 = g_Ks[b * DOUT + wid * 64 + 2 * lane + 1];
        float ss = k0 * k0 + k1 * k1;
#pragma unroll
        for (int o = 16; o > 0; o >>= 1) ss += __shfl_xor_sync(0xffffffffu, ss, o);
        float rn = rsqrtf(ss);
        kn[wid * 64 + 2 * lane]     = k0 * rn;
        kn[wid * 64 + 2 * lane + 1] = k1 * rn;
    }
    __syncthreads();

    // B fragments (cols 6,7 zero)
    unsigned kb0[8], kb1[8];
#pragma unroll
    for (int c = 0; c < 8; c++) {
        float v0 = (g < HH) ? kn[g * 64 + c * 8 + t] : 0.0f;
        float v1 = (g < HH) ? kn[g * 64 + c * 8 + t + 4] : 0.0f;
        kb0[c] = __float_as_uint(v0);
        kb1[c] = __float_as_uint(v1);
    }

    const float* __restrict__ memb = memory + (size_t)b * MEM_ELEMS;
    float* tileF = tile + wid * 16 * TSTRIDE;
    float4* tf4 = (float4*)tileF;

    float sum0 = 0.0f, sum1 = 0.0f;   // heads 2t, 2t+1

    for (int j = 0; j < 8; j++) {
        const int n0 = half * 1024 + wid * 16 + j * 128;
#pragma unroll
        for (int i = 0; i < 8; i++) {
            int idx = lane + i * 32;
            int row = idx >> 4, q = idx & 15;
            tf4[row * 17 + q] =
                *(const float4*)(memb + (size_t)(n0 + row) * MM + q * 4);
        }
        __syncwarp();

        float acc[4] = {0.f, 0.f, 0.f, 0.f};
        float ss0 = 0.f, ss1 = 0.f;
#pragma unroll
        for (int c = 0; c < 8; c++) {
            float a0 = tileF[g * TSTRIDE + c * 8 + t];
            float a1 = tileF[(g + 8) * TSTRIDE + c * 8 + t];
            float a2 = tileF[g * TSTRIDE + c * 8 + t + 4];
            float a3 = tileF[(g + 8) * TSTRIDE + c * 8 + t + 4];
            ss0 += a0 * a0 + a2 * a2;
            ss1 += a1 * a1 + a3 * a3;
            unsigned af[4] = {__float_as_uint(a0), __float_as_uint(a1),
                              __float_as_uint(a2), __float_as_uint(a3)};
            MMA_TF32(acc, af, kb0[c], kb1[c]);
        }
        ss0 += __shfl_xor_sync(0xffffffffu, ss0, 1);
        ss0 += __shfl_xor_sync(0xffffffffu, ss0, 2);
        ss1 += __shfl_xor_sync(0xffffffffu, ss1, 1);
        ss1 += __shfl_xor_sync(0xffffffffu, ss1, 2);
        float rn0 = rsqrtf(ss0), rn1 = rsqrtf(ss1);

        float e0 = __expf(acc[0] * rn0);   // head 2t,   row n0+g
        float e1 = __expf(acc[1] * rn0);   // head 2t+1, row n0+g
        float e2 = __expf(acc[2] * rn1);   // head 2t,   row n0+g+8
        float e3 = __expf(acc[3] * rn1);   // head 2t+1, row n0+g+8
        sum0 += e0 + e2;
        sum1 += e1 + e3;

        float* s0 = g_S + ((size_t)b * NN + n0 + g) * 8 + 2 * t;
        float* s1 = g_S + ((size_t)b * NN + n0 + g + 8) * 8 + 2 * t;
        *(float2*)s0 = make_float2(e0, e1);
        *(float2*)s1 = make_float2(e2, e3);
        __syncwarp();
    }

    // reduce sums across the 8 g-lanes sharing t (lane = g*4 + t)
#pragma unroll
    for (int o = 4; o < 32; o <<= 1) {
        sum0 += __shfl_xor_sync(0xffffffffu, sum0, o);
        sum1 += __shfl_xor_sync(0xffffffffu, sum1, o);
    }
    if (g == 0 && t < 3) {
        redp[wid][2 * t]     = sum0;
        redp[wid][2 * t + 1] = sum1;
    }
    __syncthreads();
    if (tid < HH) {
        float s = 0.0f;
#pragma unroll
        for (int wq = 0; wq < 8; wq++) s += redp[wq][tid];
        g_psum[(b * 2 + half) * HH + tid] = s;
    }
}

// ---------------------------------------------------------------------------
// K2c: memory update via mma, normalization folded into A-frags.
// grid (4, 256), 128 threads, no block barriers, pure streaming.
// ---------------------------------------------------------------------------
__global__ __launch_bounds__(128) void update_kernel(
    const float* __restrict__ memory, float* __restrict__ out_mem)
{
    const int b = blockIdx.y;
    const int ntile = blockIdx.x;
    const int tid = threadIdx.x, wid = tid >> 5, lane = tid & 31;
    const int g = lane >> 2, t = lane & 3;

    // softmax denominators (per-lane: only heads this lane's frags carry)
    const float i0t = 1.0f / (g_psum[(b * 2 + 0) * HH + t] +
                              g_psum[(b * 2 + 1) * HH + t]);
    const float i1t = (t < 2)
        ? 1.0f / (g_psum[(b * 2 + 0) * HH + t + 4] +
                  g_psum[(b * 2 + 1) * HH + t + 4])
        : 0.0f;

    // B fragments from e/a (rows=head, cols=m); rows 6,7 zero
    const float* __restrict__ eb = g_Es + b * DOUT;
    const float* __restrict__ ab = g_As + b * DOUT;
    unsigned eb0[8], eb1[8], ab0[8], ab1[8];
#pragma unroll
    for (int mb = 0; mb < 8; mb++) {
        eb0[mb] = __float_as_uint(eb[t * 64 + mb * 8 + g]);
        ab0[mb] = __float_as_uint(ab[t * 64 + mb * 8 + g]);
        eb1[mb] = __float_as_uint((t < 2) ? eb[(t + 4) * 64 + mb * 8 + g] : 0.0f);
        ab1[mb] = __float_as_uint((t < 2) ? ab[(t + 4) * 64 + mb * 8 + g] : 0.0f);
    }

    const float* __restrict__ memb = memory + (size_t)b * MEM_ELEMS;
    float* __restrict__ outm = out_mem + (size_t)b * MEM_ELEMS;
    const float* __restrict__ wsb = g_S + (size_t)b * NN * 8;

    for (int j = 0; j < 8; j++) {
        const int n0 = ntile * 512 + wid * 16 + j * 64;
        const float* ws = wsb + (size_t)n0 * 8;

        // A fragment: normalized weights (pad cols scaled to 0)
        unsigned af[4];
        af[0] = __float_as_uint(ws[g * 8 + t] * i0t);
        af[1] = __float_as_uint(ws[(g + 8) * 8 + t] * i0t);
        af[2] = __float_as_uint(ws[g * 8 + t + 4] * i1t);
        af[3] = __float_as_uint(ws[(g + 8) * 8 + t + 4] * i1t);

        const float* mrow0 = memb + (size_t)(n0 + g) * MM;
        const float* mrow1 = memb + (size_t)(n0 + g + 8) * MM;
        float* orow0 = outm + (size_t)(n0 + g) * MM;
        float* orow1 = outm + (size_t)(n0 + g + 8) * MM;

#pragma unroll
        for (int mbh = 0; mbh < 2; mbh++) {
            // Hoisted loads for this half (MLP 8)
            float2 mv0[4], mv1[4];
#pragma unroll
            for (int m2 = 0; m2 < 4; m2++) {
                int mb = mbh * 4 + m2;
                mv0[m2] = *(const float2*)(mrow0 + mb * 8 + 2 * t);
                mv1[m2] = *(const float2*)(mrow1 + mb * 8 + 2 * t);
            }
            float er[4][4], ad[4][4];
#pragma unroll
            for (int m2 = 0; m2 < 4; m2++) {
#pragma unroll
                for (int q = 0; q < 4; q++) { er[m2][q] = 0.f; ad[m2][q] = 0.f; }
                int mb = mbh * 4 + m2;
                MMA_TF32(er[m2], af, eb0[mb], eb1[mb]);
                MMA_TF32(ad[m2], af, ab0[mb], ab1[mb]);
            }
#pragma unroll
            for (int m2 = 0; m2 < 4; m2++) {
                int mb = mbh * 4 + m2;
                float2 o0, o1;
                o0.x = mv0[m2].x + (ad[m2][0] - mv0[m2].x * mv0[m2].x * er[m2][0]);
                o0.y = mv0[m2].y + (ad[m2][1] - mv0[m2].y * mv0[m2].y * er[m2][1]);
                o1.x = mv1[m2].x + (ad[m2][2] - mv1[m2].x * mv1[m2].x * er[m2][2]);
                o1.y = mv1[m2].y + (ad[m2][3] - mv1[m2].y * mv1[m2].y * er[m2][3]);
                *(float2*)(orow0 + mb * 8 + 2 * t) = o0;
                *(float2*)(orow1 + mb * 8 + 2 * t) = o1;
            }
        }
    }
}

// ---------------------------------------------------------------------------
// K2d: out_w writer. grid 256, 256 threads. Coalesced reads/writes only.
// ---------------------------------------------------------------------------
__global__ __launch_bounds__(256) void wout_kernel(float* __restrict__ out_w)
{
    const int b = blockIdx.x;
    const int tid = threadIdx.x;

    float inv[HH];
#pragma unroll
    for (int h = 0; h < HH; h++)
        inv[h] = 1.0f / (g_psum[(b * 2 + 0) * HH + h] +
                         g_psum[(b * 2 + 1) * HH + h]);

    const float* __restrict__ wsb = g_S + (size_t)b * NN * 8;
    float* __restrict__ owb = out_w + (size_t)b * (HH * NN);

#pragma unroll
    for (int k = 0; k < 8; k++) {
        int row = tid + k * 256;
        float4 v0 = *(const float4*)(wsb + (size_t)row * 8);
        float2 v1 = *(const float2*)(wsb + (size_t)row * 8 + 4);
        owb[0 * NN + row] = v0.x * inv[0];
        owb[1 * NN + row] = v0.y * inv[1];
        owb[2 * NN + row] = v0.z * inv[2];
        owb[3 * NN + row] = v0.w * inv[3];
        owb[4 * NN + row] = v1.x * inv[4];
        owb[5 * NN + row] = v1.y * inv[5];
    }
}

// ---------------------------------------------------------------------------
extern "C" void kernel_launch(void* const* d_in, const int* in_sizes, int n_in,
                              void* d_out, int out_size)
{
    const float* inputs = (const float*)d_in[0];
    const float* memory = (const float*)d_in[1];
    const float* w      = (const float*)d_in[2];
    const float* Wk     = (const float*)d_in[3];
    const float* bk     = (const float*)d_in[4];
    const float* We     = (const float*)d_in[5];
    const float* be     = (const float*)d_in[6];
    const float* Wa     = (const float*)d_in[7];
    const float* ba     = (const float*)d_in[8];

    float* out     = (float*)d_out;
    float* out_mem = out;                       // new_memory [B,N,M]
    float* out_w   = out + OUT_MEM_TOTAL;       // w_new      [B,H,N]

    cudaFuncSetAttribute(gemm_kernel,
                         cudaFuncAttributeMaxDynamicSharedMemorySize,
                         GEMM_SMEM_BYTES);
    dim3 g1(2, 18, SPLITK);
    gemm_kernel<<<g1, 128, GEMM_SMEM_BYTES>>>(w, inputs, Wk, We, Wa);

    reduce_act_kernel<<<(BB * Y_N) / 256, 256>>>(bk, be, ba);

    scores_kernel<<<dim3(2, BB), 256>>>(memory);

    update_kernel<<<dim3(4, BB), 128>>>(memory, out_mem);

    wout_kernel<<<BB, 256>>>(out_w);
}

// round 11
// speedup vs baseline: 1.0938x; 1.0135x over previous
#include <cuda_runtime.h>
#include <math.h>
#include <stdint.h>

// Problem constants
#define BB    256
#define HH    6
#define NN    2048
#define MM    64
#define DIN   128
#define WFLAT 12288          // H*N
#define DCAT  12416
#define DOUT  384
#define Y_N   1152           // 3*DOUT
#define MEM_ELEMS 131072     // N*M per batch
#define OUT_MEM_TOTAL 33554432  // B*N*M

// GEMM config (R7, measured 56.4us): CTA 128x64, warp 64x32, BKT=32, cp.async
#define SPLITK 16
#define BKT 32
#define BMT 128
#define BNT 64
#define ASTR 36
#define BSTR 72
#define A_TILE_F (BMT * ASTR)
#define B_TILE_F (BKT * BSTR)
#define GEMM_SMEM_BYTES ((2 * (A_TILE_F + B_TILE_F)) * 4)   // 55296

// Scratch (static device memory; no allocation)
__device__ float g_Ypart[SPLITK * (size_t)BB * Y_N];  // 18.9 MB
__device__ float g_Ks[BB * DOUT];
__device__ float g_Es[BB * DOUT];
__device__ float g_As[BB * DOUT];
__device__ float g_S[(size_t)BB * NN * 8];            // 16.8 MB exp-scores [b][n][8]
__device__ float g_psum[BB * 2 * HH];                 // per-(b,half,h) partial sums

__device__ __forceinline__ unsigned s2u(const void* p) {
    return (unsigned)__cvta_generic_to_shared(p);
}

__device__ __forceinline__ void cpa16(uint32_t dst, const void* src) {
    asm volatile("cp.async.cg.shared.global [%0], [%1], 16;" :: "r"(dst), "l"(src));
}
#define CP_COMMIT() asm volatile("cp.async.commit_group;" ::: "memory")
#define CP_WAIT1()  asm volatile("cp.async.wait_group 1;" ::: "memory")

#define MMA_TF32(c, a, b0, b1)                                                     \
    asm volatile(                                                                  \
        "mma.sync.aligned.m16n8k8.row.col.f32.tf32.tf32.f32 "                      \
        "{%0,%1,%2,%3},{%4,%5,%6,%7},{%8,%9},{%0,%1,%2,%3};"                       \
        : "+f"(c[0]), "+f"(c[1]), "+f"(c[2]), "+f"(c[3])                           \
        : "r"(a[0]), "r"(a[1]), "r"(a[2]), "r"(a[3]), "r"(b0), "r"(b1))

#define LDSM_X4(r, addr)                                                           \
    asm volatile("ldmatrix.sync.aligned.m8n8.x4.shared.b16 {%0,%1,%2,%3}, [%4];"   \
                 : "=r"(r[0]), "=r"(r[1]), "=r"(r[2]), "=r"(r[3]) : "r"(addr))

// ---------------------------------------------------------------------------
// K1: split-K tf32 GEMM (R7 verbatim)
// ---------------------------------------------------------------------------
__global__ __launch_bounds__(128) void gemm_kernel(
    const float* __restrict__ xw, const float* __restrict__ xin,
    const float* __restrict__ Wk, const float* __restrict__ We,
    const float* __restrict__ Wa)
{
    extern __shared__ float smf[];
    float* As[2] = {smf, smf + A_TILE_F};
    float* Bs[2] = {smf + 2 * A_TILE_F, smf + 2 * A_TILE_F + B_TILE_F};
    const uint32_t sA32[2] = {s2u(As[0]), s2u(As[1])};
    const uint32_t sB32[2] = {s2u(Bs[0]), s2u(Bs[1])};

    const int tid = threadIdx.x;
    const int mt = blockIdx.x, nt = blockIdx.y, z = blockIdx.z;
    const int m0 = mt * BMT;
    const int mat = nt / 6;
    const int n0col = (nt % 6) * BNT;
    const float* __restrict__ Wp = (mat == 0) ? Wk : ((mat == 1) ? We : Wa);

    const int baseT = z * 24 + min(z, 4);
    const int cnt   = 24 + (z < 4 ? 1 : 0);
    const int k0    = baseT * BKT;

    const int wid = tid >> 5, lane = tid & 31;
    const int g = lane >> 2, t = lane & 3;
    const int wm = (wid & 1) * 64, wn = (wid >> 1) * 32;

    const int aRowOff = (lane & 15) * ASTR + (lane >> 4) * 4;

    const int arow = tid >> 3;
    const int ac4  = (tid & 7) * 4;
    const int brow = tid >> 4;
    const int bc4  = (tid & 15) * 4;

    float acc[4][4][4];
#pragma unroll
    for (int i = 0; i < 4; i++)
#pragma unroll
        for (int j = 0; j < 4; j++)
#pragma unroll
            for (int q = 0; q < 4; q++) acc[i][j][q] = 0.0f;

#define LOADT(it)                                                                  \
    do {                                                                           \
        const int buf = (it) & 1;                                                  \
        int kb = k0 + (it) * BKT;                                                  \
        int kg = kb + ac4;                                                         \
        _Pragma("unroll")                                                          \
        for (int i = 0; i < 8; i++) {                                              \
            int row = arow + i * 16;                                               \
            uint32_t dst = sA32[buf] + 4u * (row * ASTR + ac4);                    \
            const float* src = (kg < WFLAT)                                        \
                ? (xw + (size_t)(m0 + row) * WFLAT + kg)                           \
                : (xin + (size_t)(m0 + row) * DIN + (kg - WFLAT));                 \
            cpa16(dst, src);                                                       \
        }                                                                          \
        _Pragma("unroll")                                                          \
        for (int i = 0; i < 4; i++) {                                              \
            int kr = brow + i * 8;                                                 \
            uint32_t dst = sB32[buf] + 4u * (kr * BSTR + bc4);                     \
            cpa16(dst, Wp + (size_t)(kb + kr) * DOUT + n0col + bc4);               \
        }                                                                          \
    } while (0)

    LOADT(0);
    CP_COMMIT();
    if (cnt > 1) LOADT(1);
    CP_COMMIT();

    for (int it = 0; it < cnt; ++it) {
        CP_WAIT1();
        __syncthreads();

        const int bf = it & 1;
        const uint32_t sA = sA32[bf];
        const float* __restrict__ Bsf = Bs[bf];
#pragma unroll
        for (int ko = 0; ko < BKT; ko += 8) {
            unsigned af[4][4];
#pragma unroll
            for (int mf = 0; mf < 4; mf++) {
                unsigned addr = sA + 4u * ((wm + mf * 16) * ASTR + aRowOff + ko);
                LDSM_X4(af[mf], addr);
            }
            unsigned bfr[4][2];
#pragma unroll
            for (int nf = 0; nf < 4; nf++) {
                int c0 = wn + nf * 8 + g;
                bfr[nf][0] = __float_as_uint(Bsf[(ko + t) * BSTR + c0]);
                bfr[nf][1] = __float_as_uint(Bsf[(ko + t + 4) * BSTR + c0]);
            }
#pragma unroll
            for (int mf = 0; mf < 4; mf++)
#pragma unroll
                for (int nf = 0; nf < 4; nf++)
                    MMA_TF32(acc[mf][nf], af[mf], bfr[nf][0], bfr[nf][1]);
        }

        __syncthreads();
        if (it + 2 < cnt) LOADT(it + 2);
        CP_COMMIT();
    }

    float* yp = g_Ypart + (size_t)z * (BB * Y_N);
#pragma unroll
    for (int mf = 0; mf < 4; mf++) {
#pragma unroll
        for (int nf = 0; nf < 4; nf++) {
            int row = m0 + wm + mf * 16 + g;
            int col = nt * BNT + wn + nf * 8 + 2 * t;
            float2 v0 = make_float2(acc[mf][nf][0], acc[mf][nf][1]);
            float2 v1 = make_float2(acc[mf][nf][2], acc[mf][nf][3]);
            *(float2*)(yp + (size_t)row * Y_N + col) = v0;
            *(float2*)(yp + (size_t)(row + 8) * Y_N + col) = v1;
        }
    }
#undef LOADT
}

// ---------------------------------------------------------------------------
// K1b: reduce split-K partials, add bias, apply sigmoid for e/a
// ---------------------------------------------------------------------------
__global__ void reduce_act_kernel(const float* __restrict__ bk,
                                  const float* __restrict__ be,
                                  const float* __restrict__ ba)
{
    int idx = blockIdx.x * blockDim.x + threadIdx.x;
    float s = 0.0f;
#pragma unroll
    for (int z = 0; z < SPLITK; z++)
        s += g_Ypart[(size_t)z * (BB * Y_N) + idx];
    int row = idx / Y_N;
    int col = idx - row * Y_N;
    int mat = col / DOUT;
    int c = col - mat * DOUT;
    if (mat == 0) {
        g_Ks[row * DOUT + c] = s + bk[c];
    } else if (mat == 1) {
        float v = s + be[c];
        g_Es[row * DOUT + c] = 1.0f / (1.0f + __expf(-v));
    } else {
        float v = s + ba[c];
        g_As[row * DOUT + c] = 1.0f / (1.0f + __expf(-v));
    }
}

// ---------------------------------------------------------------------------
// K2a: exp(cosine scores) -> g_S[b][n][8], plus per-(b,half,head) sums.
// Scores bounded in [-1,1] so exp without max-subtraction is safe.
// grid (2, 256), 256 threads (8 warps), ~36 KB smem
// ---------------------------------------------------------------------------
#define TSTRIDE 68
__global__ __launch_bounds__(256) void scores_kernel(
    const float* __restrict__ memory)
{
    __shared__ float kn[DOUT];
    __shared__ float tile[8 * 16 * TSTRIDE];
    __shared__ float redp[8][8];   // [warp][head]

    const int b = blockIdx.y;
    const int half = blockIdx.x;
    const int tid = threadIdx.x, wid = tid >> 5, lane = tid & 31;
    const int g = lane >> 2, t = lane & 3;

    // normalized k
    if (wid < HH) {
        float k0 = g_Ks[b * DOUT + wid * 64 + 2 * lane];
        float k1 = g_Ks[b * DOUT + wid * 64 + 2 * lane + 1];
        float ss = k0 * k0 + k1 * k1;
#pragma unroll
        for (int o = 16; o > 0; o >>= 1) ss += __shfl_xor_sync(0xffffffffu, ss, o);
        float rn = rsqrtf(ss);
        kn[wid * 64 + 2 * lane]     = k0 * rn;
        kn[wid * 64 + 2 * lane + 1] = k1 * rn;
    }
    __syncthreads();

    // B fragments (cols 6,7 zero)
    unsigned kb0[8], kb1[8];
#pragma unroll
    for (int c = 0; c < 8; c++) {
        float v0 = (g < HH) ? kn[g * 64 + c * 8 + t] : 0.0f;
        float v1 = (g < HH) ? kn[g * 64 + c * 8 + t + 4] : 0.0f;
        kb0[c] = __float_as_uint(v0);
        kb1[c] = __float_as_uint(v1);
    }

    const float* __restrict__ memb = memory + (size_t)b * MEM_ELEMS;
    float* tileF = tile + wid * 16 * TSTRIDE;
    float4* tf4 = (float4*)tileF;

    float sum0 = 0.0f, sum1 = 0.0f;   // heads 2t, 2t+1

    for (int j = 0; j < 8; j++) {
        const int n0 = half * 1024 + wid * 16 + j * 128;
#pragma unroll
        for (int i = 0; i < 8; i++) {
            int idx = lane + i * 32;
            int row = idx >> 4, q = idx & 15;
            tf4[row * 17 + q] =
                *(const float4*)(memb + (size_t)(n0 + row) * MM + q * 4);
        }
        __syncwarp();

        float acc[4] = {0.f, 0.f, 0.f, 0.f};
        float ss0 = 0.f, ss1 = 0.f;
#pragma unroll
        for (int c = 0; c < 8; c++) {
            float a0 = tileF[g * TSTRIDE + c * 8 + t];
            float a1 = tileF[(g + 8) * TSTRIDE + c * 8 + t];
            float a2 = tileF[g * TSTRIDE + c * 8 + t + 4];
            float a3 = tileF[(g + 8) * TSTRIDE + c * 8 + t + 4];
            ss0 += a0 * a0 + a2 * a2;
            ss1 += a1 * a1 + a3 * a3;
            unsigned af[4] = {__float_as_uint(a0), __float_as_uint(a1),
                              __float_as_uint(a2), __float_as_uint(a3)};
            MMA_TF32(acc, af, kb0[c], kb1[c]);
        }
        ss0 += __shfl_xor_sync(0xffffffffu, ss0, 1);
        ss0 += __shfl_xor_sync(0xffffffffu, ss0, 2);
        ss1 += __shfl_xor_sync(0xffffffffu, ss1, 1);
        ss1 += __shfl_xor_sync(0xffffffffu, ss1, 2);
        float rn0 = rsqrtf(ss0), rn1 = rsqrtf(ss1);

        float e0 = __expf(acc[0] * rn0);   // head 2t,   row n0+g
        float e1 = __expf(acc[1] * rn0);   // head 2t+1, row n0+g
        float e2 = __expf(acc[2] * rn1);   // head 2t,   row n0+g+8
        float e3 = __expf(acc[3] * rn1);   // head 2t+1, row n0+g+8
        sum0 += e0 + e2;
        sum1 += e1 + e3;

        float* s0 = g_S + ((size_t)b * NN + n0 + g) * 8 + 2 * t;
        float* s1 = g_S + ((size_t)b * NN + n0 + g + 8) * 8 + 2 * t;
        *(float2*)s0 = make_float2(e0, e1);
        *(float2*)s1 = make_float2(e2, e3);
        __syncwarp();
    }

    // reduce sums across the 8 g-lanes sharing t (lane = g*4 + t)
#pragma unroll
    for (int o = 4; o < 32; o <<= 1) {
        sum0 += __shfl_xor_sync(0xffffffffu, sum0, o);
        sum1 += __shfl_xor_sync(0xffffffffu, sum1, o);
    }
    if (g == 0 && t < 3) {
        redp[wid][2 * t]     = sum0;
        redp[wid][2 * t + 1] = sum1;
    }
    __syncthreads();
    if (tid < HH) {
        float s = 0.0f;
#pragma unroll
        for (int wq = 0; wq < 8; wq++) s += redp[wq][tid];
        g_psum[(b * 2 + half) * HH + tid] = s;
    }
}

// ---------------------------------------------------------------------------
// K2c: memory update via mma, normalization folded into A-frags.
// grid (16, 256), 128 threads. Reversed batch order for L2 reuse of the
// scores-kernel stream; e/a loaded per-MMA from L1 (low regs -> high occ);
// evict-first policy on the single-use memory stream.
// ---------------------------------------------------------------------------
__global__ __launch_bounds__(128) void update_kernel(
    const float* __restrict__ memory, float* __restrict__ out_mem)
{
    const int b = (BB - 1) - blockIdx.y;    // reverse: reuse tail of L2 stream
    const int ntile = blockIdx.x;           // 0..15, 128 rows each
    const int tid = threadIdx.x, wid = tid >> 5, lane = tid & 31;
    const int g = lane >> 2, t = lane & 3;

    // softmax denominators (per-lane: only heads this lane's frags carry)
    const float i0t = 1.0f / (g_psum[(b * 2 + 0) * HH + t] +
                              g_psum[(b * 2 + 1) * HH + t]);
    const float i1t = (t < 2)
        ? 1.0f / (g_psum[(b * 2 + 0) * HH + t + 4] +
                  g_psum[(b * 2 + 1) * HH + t + 4])
        : 0.0f;

    const float* __restrict__ eb = g_Es + b * DOUT;   // L1/L2 resident (1.5KB)
    const float* __restrict__ ab = g_As + b * DOUT;

    const float* __restrict__ memb = memory + (size_t)b * MEM_ELEMS;
    float* __restrict__ outm = out_mem + (size_t)b * MEM_ELEMS;
    const float* __restrict__ wsb = g_S + (size_t)b * NN * 8;

#pragma unroll
    for (int j = 0; j < 2; j++) {
        const int n0 = ntile * 128 + wid * 16 + j * 64;
        const float* ws = wsb + (size_t)n0 * 8;

        // A fragment: normalized weights (pad cols scaled to 0)
        unsigned af[4];
        af[0] = __float_as_uint(ws[g * 8 + t] * i0t);
        af[1] = __float_as_uint(ws[(g + 8) * 8 + t] * i0t);
        af[2] = __float_as_uint(ws[g * 8 + t + 4] * i1t);
        af[3] = __float_as_uint(ws[(g + 8) * 8 + t + 4] * i1t);

        const float* mrow0 = memb + (size_t)(n0 + g) * MM;
        const float* mrow1 = memb + (size_t)(n0 + g + 8) * MM;
        float* orow0 = outm + (size_t)(n0 + g) * MM;
        float* orow1 = outm + (size_t)(n0 + g + 8) * MM;

#pragma unroll
        for (int mbh = 0; mbh < 2; mbh++) {
            // Hoisted evict-first loads for this half (MLP 8)
            float2 mv0[4], mv1[4];
#pragma unroll
            for (int m2 = 0; m2 < 4; m2++) {
                int mb = mbh * 4 + m2;
                mv0[m2] = __ldcs((const float2*)(mrow0 + mb * 8 + 2 * t));
                mv1[m2] = __ldcs((const float2*)(mrow1 + mb * 8 + 2 * t));
            }
#pragma unroll
            for (int m2 = 0; m2 < 4; m2++) {
                int mb = mbh * 4 + m2;
                // e/a B-fragments loaded per-MMA (L1 hit), not held in regs
                unsigned e0 = __float_as_uint(eb[t * 64 + mb * 8 + g]);
                unsigned a0 = __float_as_uint(ab[t * 64 + mb * 8 + g]);
                unsigned e1 = __float_as_uint(
                    (t < 2) ? eb[(t + 4) * 64 + mb * 8 + g] : 0.0f);
                unsigned a1 = __float_as_uint(
                    (t < 2) ? ab[(t + 4) * 64 + mb * 8 + g] : 0.0f);

                float er[4] = {0.f, 0.f, 0.f, 0.f};
                float ad[4] = {0.f, 0.f, 0.f, 0.f};
                MMA_TF32(er, af, e0, e1);
                MMA_TF32(ad, af, a0, a1);

                float2 o0, o1;
                o0.x = mv0[m2].x + (ad[0] - mv0[m2].x * mv0[m2].x * er[0]);
                o0.y = mv0[m2].y + (ad[1] - mv0[m2].y * mv0[m2].y * er[1]);
                o1.x = mv1[m2].x + (ad[2] - mv1[m2].x * mv1[m2].x * er[2]);
                o1.y = mv1[m2].y + (ad[3] - mv1[m2].y * mv1[m2].y * er[3]);
                __stcs((float2*)(orow0 + mb * 8 + 2 * t), o0);
                __stcs((float2*)(orow1 + mb * 8 + 2 * t), o1);
            }
        }
    }
}

// ---------------------------------------------------------------------------
// K2d: out_w writer. grid 256, 256 threads. Coalesced reads/writes only.
// ---------------------------------------------------------------------------
__global__ __launch_bounds__(256) void wout_kernel(float* __restrict__ out_w)
{
    const int b = blockIdx.x;
    const int tid = threadIdx.x;

    float inv[HH];
#pragma unroll
    for (int h = 0; h < HH; h++)
        inv[h] = 1.0f / (g_psum[(b * 2 + 0) * HH + h] +
                         g_psum[(b * 2 + 1) * HH + h]);

    const float* __restrict__ wsb = g_S + (size_t)b * NN * 8;
    float* __restrict__ owb = out_w + (size_t)b * (HH * NN);

#pragma unroll
    for (int k = 0; k < 8; k++) {
        int row = tid + k * 256;
        float4 v0 = *(const float4*)(wsb + (size_t)row * 8);
        float2 v1 = *(const float2*)(wsb + (size_t)row * 8 + 4);
        owb[0 * NN + row] = v0.x * inv[0];
        owb[1 * NN + row] = v0.y * inv[1];
        owb[2 * NN + row] = v0.z * inv[2];
        owb[3 * NN + row] = v0.w * inv[3];
        owb[4 * NN + row] = v1.x * inv[4];
        owb[5 * NN + row] = v1.y * inv[5];
    }
}

// ---------------------------------------------------------------------------
extern "C" void kernel_launch(void* const* d_in, const int* in_sizes, int n_in,
                              void* d_out, int out_size)
{
    const float* inputs = (const float*)d_in[0];
    const float* memory = (const float*)d_in[1];
    const float* w      = (const float*)d_in[2];
    const float* Wk     = (const float*)d_in[3];
    const float* bk     = (const float*)d_in[4];
    const float* We     = (const float*)d_in[5];
    const float* be     = (const float*)d_in[6];
    const float* Wa     = (const float*)d_in[7];
    const float* ba     = (const float*)d_in[8];

    float* out     = (float*)d_out;
    float* out_mem = out;                       // new_memory [B,N,M]
    float* out_w   = out + OUT_MEM_TOTAL;       // w_new      [B,H,N]

    cudaFuncSetAttribute(gemm_kernel,
                         cudaFuncAttributeMaxDynamicSharedMemorySize,
                         GEMM_SMEM_BYTES);
    dim3 g1(2, 18, SPLITK);
    gemm_kernel<<<g1, 128, GEMM_SMEM_BYTES>>>(w, inputs, Wk, We, Wa);

    reduce_act_kernel<<<(BB * Y_N) / 256, 256>>>(bk, be, ba);

    scores_kernel<<<dim3(2, BB), 256>>>(memory);

    update_kernel<<<dim3(16, BB), 128>>>(memory, out_mem);

    wout_kernel<<<BB, 256>>>(out_w);
}